// round 14
// baseline (speedup 1.0000x reference)
#include <cuda_runtime.h>
#include <cuda_bf16.h>
#include <math.h>
#include <stdint.h>

#define SEQ 2048
#define HIDDEN 4096
#define NQH 32
#define NKVH 8
#define HD 128
#define QDIM (NQH*HD)      /* 4096 */
#define KVDIM (NKVH*HD)    /* 1024 */
#define WINDOW 1024
#define SCALING 0.08838834764831845f

/* scratch (allocation-free rule: __device__ globals) */
__device__ float g_q[SEQ*QDIM];
__device__ float g_k[SEQ*KVDIM];
__device__ float g_v[SEQ*KVDIM];
__device__ float g_attn[SEQ*QDIM];
/* tf32-pre-rounded GEMM operands */
__device__ float g_hs[SEQ*HIDDEN];
__device__ float g_wq[HIDDEN*QDIM];
__device__ float g_wk[HIDDEN*KVDIM];
__device__ float g_wv[HIDDEN*KVDIM];
__device__ float g_wo[QDIM*HIDDEN];

__device__ __forceinline__ float roundtf(float x) {
    float r;
    asm("cvt.rna.tf32.f32 %0, %1;" : "=f"(r) : "f"(x));
    return r;
}

/* elementwise tf32 rounding pass */
__global__ void round_tf32_kernel(const float* __restrict__ in, float* __restrict__ out, int n4)
{
    int i = blockIdx.x * blockDim.x + threadIdx.x;
    if (i >= n4) return;
    float4 v = ((const float4*)in)[i];
    v.x = roundtf(v.x); v.y = roundtf(v.y);
    v.z = roundtf(v.z); v.w = roundtf(v.w);
    ((float4*)out)[i] = v;
}

/* ------- TF32 GEMM: 128x256 CTA, 16 warps (64x32 each, 4/SMSP), 4-stage cp.async ------- */
/* Inputs MUST be tf32-pre-rounded fp32. 4 warps/SMSP covers MMA latency (R11 ncu: 2
   warps/SMSP -> tensor pipe 50%). Single __syncthreads per k-iteration.                  */

#define GBM 128
#define GBN 256
#define GBK 32
#define ASTR 36                    /* floats */
#define BSTR 264                   /* floats; 264 mod 32 = 8 */
#define A_STAGE (GBM*ASTR)         /* 4608  */
#define B_STAGE (GBK*BSTR)         /* 8448  */
#define STG 4
#define GEMM_SMEM (STG*(A_STAGE+B_STAGE)*4)   /* 208896 B */

__device__ __forceinline__ void cp_async16(float* smem_ptr, const float* gptr) {
    uint32_t s = (uint32_t)__cvta_generic_to_shared(smem_ptr);
    asm volatile("cp.async.cg.shared.global [%0], [%1], 16;" :: "r"(s), "l"(gptr));
}

__device__ __forceinline__ void gemm_body(
    const float* __restrict__ A, const float* __restrict__ B, float* __restrict__ C,
    int ldb, int ldc, int K, int bm0, int bn0, float* sm)
{
    float* As = sm;                    /* [STG][128][ASTR] */
    float* Bs = sm + STG * A_STAGE;    /* [STG][32][BSTR]  */

    const int tid  = threadIdx.x;      /* 0..511 */
    const int lane = tid & 31;
    const int wid  = tid >> 5;         /* 0..15  */
    const int wm   = (wid & 1) * 64;   /* 0 or 64 */
    const int wn   = (wid >> 1) * 32;  /* 0..224  */
    const int t4   = lane & 3;
    const int g    = lane >> 2;

    float acc[4][4][4];
    #pragma unroll
    for (int i = 0; i < 4; i++)
        #pragma unroll
        for (int j = 0; j < 4; j++)
            #pragma unroll
            for (int r = 0; r < 4; r++) acc[i][j][r] = 0.f;

    /* staging maps (512 threads): A 1024 chunks (2/thread), B 2048 chunks (4/thread) */
    const int ar = tid >> 2;          /* 0..127 */
    const int ac = (tid & 3) * 2;     /* chunk base 0,2,4,6 */
    const int br = tid >> 4;          /* 0..31  */
    const int bc = tid & 15;          /* 0..15  */

    const int T = K / GBK;

    #define STAGE_TILE(ti, buf) do {                                              \
        const int _k0 = (ti) * GBK;                                               \
        const float* _Ag = A + (size_t)(bm0 + ar) * K + _k0;                      \
        _Pragma("unroll")                                                         \
        for (int s = 0; s < 2; s++)                                               \
            cp_async16(&As[(buf)*A_STAGE + ar*ASTR + (ac + s)*4], _Ag + (ac + s)*4);\
        const float* _Bg = B + (size_t)(_k0 + br) * ldb + bn0;                    \
        _Pragma("unroll")                                                         \
        for (int s = 0; s < 4; s++)                                               \
            cp_async16(&Bs[(buf)*B_STAGE + br*BSTR + (bc + s*16)*4], _Bg + (bc + s*16)*4);\
    } while (0)

    STAGE_TILE(0, 0);
    asm volatile("cp.async.commit_group;");
    STAGE_TILE(1, 1);
    asm volatile("cp.async.commit_group;");

    for (int t = 0; t < T; t++) {
        const int buf = t & 3;
        if (t + 2 < T)
            STAGE_TILE(t + 2, (t + 2) & 3);
        asm volatile("cp.async.commit_group;");   /* uniform group count (may be empty) */
        asm volatile("cp.async.wait_group 2;");   /* group t complete */
        __syncthreads();                          /* single barrier per iteration */

        const uint32_t* Ab = (const uint32_t*)(As + buf * A_STAGE);
        const uint32_t* Bb = (const uint32_t*)(Bs + buf * B_STAGE);

        #pragma unroll
        for (int ks = 0; ks < 4; ks++) {
            const int kk = ks * 8;
            uint32_t a[4][4], b[4][2];
            #pragma unroll
            for (int i = 0; i < 4; i++) {
                const int mr = wm + i * 16 + g;
                a[i][0] = Ab[mr * ASTR + kk + t4];
                a[i][1] = Ab[(mr + 8) * ASTR + kk + t4];
                a[i][2] = Ab[mr * ASTR + kk + t4 + 4];
                a[i][3] = Ab[(mr + 8) * ASTR + kk + t4 + 4];
            }
            #pragma unroll
            for (int j = 0; j < 4; j++) {
                const int nc = wn + j * 8 + g;
                b[j][0] = Bb[(kk + t4) * BSTR + nc];
                b[j][1] = Bb[(kk + t4 + 4) * BSTR + nc];
            }
            #pragma unroll
            for (int i = 0; i < 4; i++)
                #pragma unroll
                for (int j = 0; j < 4; j++) {
                    asm volatile(
                        "mma.sync.aligned.m16n8k8.row.col.f32.tf32.tf32.f32 "
                        "{%0,%1,%2,%3}, {%4,%5,%6,%7}, {%8,%9}, {%0,%1,%2,%3};"
                        : "+f"(acc[i][j][0]), "+f"(acc[i][j][1]),
                          "+f"(acc[i][j][2]), "+f"(acc[i][j][3])
                        : "r"(a[i][0]), "r"(a[i][1]), "r"(a[i][2]), "r"(a[i][3]),
                          "r"(b[j][0]), "r"(b[j][1]));
                }
        }
    }
    #undef STAGE_TILE

    #pragma unroll
    for (int i = 0; i < 4; i++) {
        int row0 = bm0 + wm + i * 16 + g;
        #pragma unroll
        for (int j = 0; j < 4; j++) {
            int col = bn0 + wn + j * 8 + 2 * t4;
            *(float2*)(C + (size_t)row0 * ldc + col)       = make_float2(acc[i][j][0], acc[i][j][1]);
            *(float2*)(C + (size_t)(row0 + 8) * ldc + col) = make_float2(acc[i][j][2], acc[i][j][3]);
        }
    }
}

/* fused QKV: grid.x = 24 (16 Q cols + 4 K + 4 V), grid.y = 16 */
__global__ __launch_bounds__(512, 1) void qkv_gemm_kernel()
{
    extern __shared__ float sm[];
    const int bx = blockIdx.x;
    const int bm0 = blockIdx.y * GBM;
    if (bx < 16)
        gemm_body(g_hs, g_wq, g_q, QDIM, QDIM, HIDDEN, bm0, bx * GBN, sm);
    else if (bx < 20)
        gemm_body(g_hs, g_wk, g_k, KVDIM, KVDIM, HIDDEN, bm0, (bx - 16) * GBN, sm);
    else
        gemm_body(g_hs, g_wv, g_v, KVDIM, KVDIM, HIDDEN, bm0, (bx - 20) * GBN, sm);
}

__global__ __launch_bounds__(512, 1) void o_gemm_kernel(float* __restrict__ out)
{
    extern __shared__ float sm[];
    gemm_body(g_attn, g_wo, out, HIDDEN, HIDDEN, QDIM, blockIdx.y * GBM, blockIdx.x * GBN, sm);
}

/* ------------------------- RoPE (NeoX) ------------------------- */
__global__ void rope_kernel(float* x, const int* __restrict__ positions, int nheads)
{
    int idx = blockIdx.x * blockDim.x + threadIdx.x;
    int total = SEQ * nheads * (HD / 2);
    if (idx >= total) return;
    int i = idx & 63;
    int h = (idx >> 6) % nheads;
    int s = idx / (64 * nheads);
    float inv = powf(1000000.0f, -(float)i * (1.0f / 64.0f));
    float f = (float)positions[s] * inv;
    float c = cosf(f), sn = sinf(f);
    float* base = x + ((size_t)s * nheads + h) * HD;
    float x1 = base[i], x2 = base[i + 64];
    base[i]      = x1 * c - x2 * sn;
    base[i + 64] = x2 * c + x1 * sn;
}

/* ------------------------- Attention: bf16x3 tensor-core flash ------------------------- */
#define AQT 128
#define AKT 64
#define KPAD 68
#define VPAD 136

#define MMA_BF16(c, a0,a1,a2,a3, b0,b1)                                      \
    asm volatile("mma.sync.aligned.m16n8k16.row.col.f32.bf16.bf16.f32 "      \
        "{%0,%1,%2,%3}, {%4,%5,%6,%7}, {%8,%9}, {%0,%1,%2,%3};"              \
        : "+f"(c[0]), "+f"(c[1]), "+f"(c[2]), "+f"(c[3])                     \
        : "r"(a0), "r"(a1), "r"(a2), "r"(a3), "r"(b0), "r"(b1))

__device__ __forceinline__ void split2(float x, float y, uint32_t& hi, uint32_t& lo) {
    __nv_bfloat162 h = __float22bfloat162_rn(make_float2(x, y));
    float rx = x - __bfloat162float(h.x);
    float ry = y - __bfloat162float(h.y);
    __nv_bfloat162 l = __float22bfloat162_rn(make_float2(rx, ry));
    hi = *(uint32_t*)&h;
    lo = *(uint32_t*)&l;
}

__global__ __launch_bounds__(256, 1) void attn_mma_kernel(const float* __restrict__ sink)
{
    extern __shared__ uint32_t smw[];
    uint32_t* Qh = smw;
    uint32_t* Ql = Qh + AQT * KPAD;
    uint32_t* Kh = Ql + AQT * KPAD;
    uint32_t* Kl = Kh + AKT * KPAD;
    uint32_t* Vh = Kl + AKT * KPAD;
    uint32_t* Vl = Vh + (AKT/2) * VPAD;

    const int h   = blockIdx.y;
    const int q0  = blockIdx.x * AQT;
    const int kvh = h >> 2;
    const int tid = threadIdx.x;
    const int lane = tid & 31;
    const int wid  = tid >> 5;
    const int wrow = wid * 16;
    const int t4   = lane & 3;
    const int g    = lane >> 2;

    {
        const float* Qg = g_q + (size_t)q0 * QDIM + h * HD;
        #pragma unroll
        for (int it = 0; it < 16; it++) {
            int slot = tid + it * 256;
            int r = slot >> 5, d4 = slot & 31;
            float4 v = *(const float4*)(Qg + (size_t)r * QDIM + d4 * 4);
            uint32_t h01, l01, h23, l23;
            split2(v.x, v.y, h01, l01);
            split2(v.z, v.w, h23, l23);
            Qh[r * KPAD + d4 * 2]     = h01;
            Qh[r * KPAD + d4 * 2 + 1] = h23;
            Ql[r * KPAD + d4 * 2]     = l01;
            Ql[r * KPAD + d4 * 2 + 1] = l23;
        }
    }

    float o[16][4];
    #pragma unroll
    for (int i = 0; i < 16; i++)
        #pragma unroll
        for (int r = 0; r < 4; r++) o[i][r] = 0.f;
    float l0 = 0.f, l1 = 0.f;

    int jlo = q0 - (WINDOW - 1);
    if (jlo < 0) jlo = 0;
    int kt0 = (jlo / AKT) * AKT;

    const int qi0 = q0 + wrow + g;
    const int qi1 = qi0 + 8;

    for (int kt = kt0; kt < q0 + AQT; kt += AKT) {
        __syncthreads();
        {
            const float* Kg = g_k + (size_t)kt * KVDIM + kvh * HD;
            #pragma unroll
            for (int it = 0; it < 8; it++) {
                int slot = tid + it * 256;
                int r = slot >> 5, d4 = slot & 31;
                float4 v = *(const float4*)(Kg + (size_t)r * KVDIM + d4 * 4);
                uint32_t h01, l01, h23, l23;
                split2(v.x, v.y, h01, l01);
                split2(v.z, v.w, h23, l23);
                Kh[r * KPAD + d4 * 2]     = h01;
                Kh[r * KPAD + d4 * 2 + 1] = h23;
                Kl[r * KPAD + d4 * 2]     = l01;
                Kl[r * KPAD + d4 * 2 + 1] = l23;
            }
        }
        {
            const float* Vg = g_v + (size_t)kt * KVDIM + kvh * HD;
            #pragma unroll
            for (int it = 0; it < 4; it++) {
                int slot = tid + it * 256;
                int rp = slot >> 5, d4 = slot & 31;
                float4 v0 = *(const float4*)(Vg + (size_t)(2 * rp) * KVDIM + d4 * 4);
                float4 v1 = *(const float4*)(Vg + (size_t)(2 * rp + 1) * KVDIM + d4 * 4);
                const float* a = &v0.x;
                const float* b = &v1.x;
                #pragma unroll
                for (int jj = 0; jj < 4; jj++) {
                    uint32_t hi, lo;
                    split2(a[jj], b[jj], hi, lo);
                    Vh[rp * VPAD + d4 * 4 + jj] = hi;
                    Vl[rp * VPAD + d4 * 4 + jj] = lo;
                }
            }
        }
        __syncthreads();

        float s[8][4];
        #pragma unroll
        for (int nt = 0; nt < 8; nt++)
            #pragma unroll
            for (int r = 0; r < 4; r++) s[nt][r] = 0.f;

        #pragma unroll
        for (int kk = 0; kk < 8; kk++) {
            const int kw = kk * 8;
            uint32_t ah0 = Qh[(wrow + g)     * KPAD + kw + t4];
            uint32_t ah1 = Qh[(wrow + g + 8) * KPAD + kw + t4];
            uint32_t ah2 = Qh[(wrow + g)     * KPAD + kw + t4 + 4];
            uint32_t ah3 = Qh[(wrow + g + 8) * KPAD + kw + t4 + 4];
            uint32_t al0 = Ql[(wrow + g)     * KPAD + kw + t4];
            uint32_t al1 = Ql[(wrow + g + 8) * KPAD + kw + t4];
            uint32_t al2 = Ql[(wrow + g)     * KPAD + kw + t4 + 4];
            uint32_t al3 = Ql[(wrow + g + 8) * KPAD + kw + t4 + 4];
            #pragma unroll
            for (int nt = 0; nt < 8; nt++) {
                const int krow = nt * 8 + g;
                uint32_t bh0 = Kh[krow * KPAD + kw + t4];
                uint32_t bh1 = Kh[krow * KPAD + kw + t4 + 4];
                uint32_t bl0 = Kl[krow * KPAD + kw + t4];
                uint32_t bl1 = Kl[krow * KPAD + kw + t4 + 4];
                MMA_BF16(s[nt], ah0, ah1, ah2, ah3, bh0, bh1);
                MMA_BF16(s[nt], ah0, ah1, ah2, ah3, bl0, bl1);
                MMA_BF16(s[nt], al0, al1, al2, al3, bh0, bh1);
            }
        }

        #pragma unroll
        for (int nt = 0; nt < 8; nt++) {
            int c0 = kt + nt * 8 + 2 * t4;
            int c1 = c0 + 1;
            float p0 = (c0 <= qi0 && qi0 - c0 < WINDOW) ? __expf(s[nt][0] * SCALING) : 0.f;
            float p1 = (c1 <= qi0 && qi0 - c1 < WINDOW) ? __expf(s[nt][1] * SCALING) : 0.f;
            float p2 = (c0 <= qi1 && qi1 - c0 < WINDOW) ? __expf(s[nt][2] * SCALING) : 0.f;
            float p3 = (c1 <= qi1 && qi1 - c1 < WINDOW) ? __expf(s[nt][3] * SCALING) : 0.f;
            l0 += p0 + p1;
            l1 += p2 + p3;
            s[nt][0] = p0; s[nt][1] = p1; s[nt][2] = p2; s[nt][3] = p3;
        }

        #pragma unroll
        for (int ks = 0; ks < 4; ks++) {
            uint32_t ah0, al0, ah1, al1, ah2, al2, ah3, al3;
            split2(s[2*ks][0],   s[2*ks][1],   ah0, al0);
            split2(s[2*ks][2],   s[2*ks][3],   ah1, al1);
            split2(s[2*ks+1][0], s[2*ks+1][1], ah2, al2);
            split2(s[2*ks+1][2], s[2*ks+1][3], ah3, al3);
            #pragma unroll
            for (int nt = 0; nt < 16; nt++) {
                uint32_t bh0 = Vh[(ks * 8 + t4)     * VPAD + nt * 8 + g];
                uint32_t bh1 = Vh[(ks * 8 + t4 + 4) * VPAD + nt * 8 + g];
                uint32_t bl0 = Vl[(ks * 8 + t4)     * VPAD + nt * 8 + g];
                uint32_t bl1 = Vl[(ks * 8 + t4 + 4) * VPAD + nt * 8 + g];
                MMA_BF16(o[nt], ah0, ah1, ah2, ah3, bh0, bh1);
                MMA_BF16(o[nt], ah0, ah1, ah2, ah3, bl0, bl1);
                MMA_BF16(o[nt], al0, al1, al2, al3, bh0, bh1);
            }
        }
    }

    l0 += __shfl_xor_sync(0xffffffffu, l0, 1);
    l0 += __shfl_xor_sync(0xffffffffu, l0, 2);
    l1 += __shfl_xor_sync(0xffffffffu, l1, 1);
    l1 += __shfl_xor_sync(0xffffffffu, l1, 2);
    float sk = __expf(sink[h]);
    float inv0 = 1.0f / (l0 + sk);
    float inv1 = 1.0f / (l1 + sk);

    /* store tf32-rounded so the O-projection GEMM can consume raw bits */
    float* out0 = g_attn + (size_t)qi0 * QDIM + h * HD;
    float* out1 = g_attn + (size_t)qi1 * QDIM + h * HD;
    #pragma unroll
    for (int nt = 0; nt < 16; nt++) {
        int d = nt * 8 + 2 * t4;
        *(float2*)(out0 + d) = make_float2(roundtf(o[nt][0] * inv0), roundtf(o[nt][1] * inv0));
        *(float2*)(out1 + d) = make_float2(roundtf(o[nt][2] * inv1), roundtf(o[nt][3] * inv1));
    }
}

/* ------------------------- launch ------------------------- */
extern "C" void kernel_launch(void* const* d_in, const int* in_sizes, int n_in,
                              void* d_out, int out_size)
{
    const float* hs   = (const float*)d_in[0];
    const int*   pos  = (const int*)d_in[1];
    const float* wq   = (const float*)d_in[2];
    const float* wk   = (const float*)d_in[3];
    const float* wv   = (const float*)d_in[4];
    const float* wo   = (const float*)d_in[5];
    const float* sink = (const float*)d_in[6];
    float* out = (float*)d_out;

    float *q_ptr, *k_ptr, *hs_ptr, *wq_ptr, *wk_ptr, *wv_ptr, *wo_ptr;
    cudaGetSymbolAddress((void**)&q_ptr, g_q);
    cudaGetSymbolAddress((void**)&k_ptr, g_k);
    cudaGetSymbolAddress((void**)&hs_ptr, g_hs);
    cudaGetSymbolAddress((void**)&wq_ptr, g_wq);
    cudaGetSymbolAddress((void**)&wk_ptr, g_wk);
    cudaGetSymbolAddress((void**)&wv_ptr, g_wv);
    cudaGetSymbolAddress((void**)&wo_ptr, g_wo);

    cudaFuncSetAttribute(qkv_gemm_kernel, cudaFuncAttributeMaxDynamicSharedMemorySize, GEMM_SMEM);
    cudaFuncSetAttribute(o_gemm_kernel,  cudaFuncAttributeMaxDynamicSharedMemorySize, GEMM_SMEM);

    /* tf32 pre-rounding of GEMM inputs */
    round_tf32_kernel<<<(SEQ*HIDDEN/4 + 255)/256, 256>>>(hs, hs_ptr, SEQ*HIDDEN/4);
    round_tf32_kernel<<<(HIDDEN*QDIM/4 + 255)/256, 256>>>(wq, wq_ptr, HIDDEN*QDIM/4);
    round_tf32_kernel<<<(HIDDEN*KVDIM/4 + 255)/256, 256>>>(wk, wk_ptr, HIDDEN*KVDIM/4);
    round_tf32_kernel<<<(HIDDEN*KVDIM/4 + 255)/256, 256>>>(wv, wv_ptr, HIDDEN*KVDIM/4);
    round_tf32_kernel<<<(QDIM*HIDDEN/4 + 255)/256, 256>>>(wo, wo_ptr, QDIM*HIDDEN/4);

    /* fused QKV projection (512 threads, 4 warps/SMSP) */
    qkv_gemm_kernel<<<dim3(24, SEQ / GBM), 512, GEMM_SMEM>>>();

    /* RoPE */
    {
        int tq = SEQ * NQH * (HD / 2);
        rope_kernel<<<(tq + 255) / 256, 256>>>(q_ptr, pos, NQH);
        int tk = SEQ * NKVH * (HD / 2);
        rope_kernel<<<(tk + 255) / 256, 256>>>(k_ptr, pos, NKVH);
    }

    /* attention (bf16x3 tensor cores) */
    {
        int smem_words = 2 * AQT * KPAD + 2 * AKT * KPAD + 2 * (AKT/2) * VPAD;
        int smem = smem_words * 4;
        cudaFuncSetAttribute(attn_mma_kernel, cudaFuncAttributeMaxDynamicSharedMemorySize, smem);
        attn_mma_kernel<<<dim3(SEQ / AQT, NQH), 256, smem>>>(sink);
    }

    /* output projection */
    o_gemm_kernel<<<dim3(HIDDEN / GBN, SEQ / GBM), 512, GEMM_SMEM>>>(out);
}

// round 15
// speedup vs baseline: 1.0014x; 1.0014x over previous
#include <cuda_runtime.h>
#include <cuda_bf16.h>
#include <math.h>
#include <stdint.h>

#define SEQ 2048
#define HIDDEN 4096
#define NQH 32
#define NKVH 8
#define HD 128
#define QDIM (NQH*HD)      /* 4096 */
#define KVDIM (NKVH*HD)    /* 1024 */
#define WINDOW 1024
#define SCALING 0.08838834764831845f

/* scratch (allocation-free rule: __device__ globals) */
__device__ float g_q[SEQ*QDIM];
__device__ float g_k[SEQ*KVDIM];
__device__ float g_v[SEQ*KVDIM];
__device__ float g_attn[SEQ*QDIM];
/* tf32-pre-rounded GEMM operands */
__device__ float g_hs[SEQ*HIDDEN];
__device__ float g_wq[HIDDEN*QDIM];
__device__ float g_wk[HIDDEN*KVDIM];
__device__ float g_wv[HIDDEN*KVDIM];
__device__ float g_wo[QDIM*HIDDEN];

__device__ __forceinline__ float roundtf(float x) {
    float r;
    asm("cvt.rna.tf32.f32 %0, %1;" : "=f"(r) : "f"(x));
    return r;
}

/* elementwise tf32 rounding pass */
__global__ void round_tf32_kernel(const float* __restrict__ in, float* __restrict__ out, int n4)
{
    int i = blockIdx.x * blockDim.x + threadIdx.x;
    if (i >= n4) return;
    float4 v = ((const float4*)in)[i];
    v.x = roundtf(v.x); v.y = roundtf(v.y);
    v.z = roundtf(v.z); v.w = roundtf(v.w);
    ((float4*)out)[i] = v;
}

/* ------- TF32 GEMM: 128x256 CTA, 16 warps (64x32 each, 4/SMSP), 4-stage cp.async ------- */
/* Inputs MUST be tf32-pre-rounded fp32. 4 warps/SMSP covers MMA latency (R11 ncu: 2
   warps/SMSP -> tensor pipe 50%). Single __syncthreads per k-iteration.                  */

#define GBM 128
#define GBN 256
#define GBK 32
#define ASTR 36                    /* floats */
#define BSTR 264                   /* floats; 264 mod 32 = 8 */
#define A_STAGE (GBM*ASTR)         /* 4608  */
#define B_STAGE (GBK*BSTR)         /* 8448  */
#define STG 4
#define GEMM_SMEM (STG*(A_STAGE+B_STAGE)*4)   /* 208896 B */

__device__ __forceinline__ void cp_async16(float* smem_ptr, const float* gptr) {
    uint32_t s = (uint32_t)__cvta_generic_to_shared(smem_ptr);
    asm volatile("cp.async.cg.shared.global [%0], [%1], 16;" :: "r"(s), "l"(gptr));
}

__device__ __forceinline__ void gemm_body(
    const float* __restrict__ A, const float* __restrict__ B, float* __restrict__ C,
    int ldb, int ldc, int K, int bm0, int bn0, float* sm)
{
    float* As = sm;                    /* [STG][128][ASTR] */
    float* Bs = sm + STG * A_STAGE;    /* [STG][32][BSTR]  */

    const int tid  = threadIdx.x;      /* 0..511 */
    const int lane = tid & 31;
    const int wid  = tid >> 5;         /* 0..15  */
    const int wm   = (wid & 1) * 64;   /* 0 or 64 */
    const int wn   = (wid >> 1) * 32;  /* 0..224  */
    const int t4   = lane & 3;
    const int g    = lane >> 2;

    float acc[4][4][4];
    #pragma unroll
    for (int i = 0; i < 4; i++)
        #pragma unroll
        for (int j = 0; j < 4; j++)
            #pragma unroll
            for (int r = 0; r < 4; r++) acc[i][j][r] = 0.f;

    /* staging maps (512 threads): A 1024 chunks (2/thread), B 2048 chunks (4/thread) */
    const int ar = tid >> 2;          /* 0..127 */
    const int ac = (tid & 3) * 2;     /* chunk base 0,2,4,6 */
    const int br = tid >> 4;          /* 0..31  */
    const int bc = tid & 15;          /* 0..15  */

    const int T = K / GBK;

    #define STAGE_TILE(ti, buf) do {                                              \
        const int _k0 = (ti) * GBK;                                               \
        const float* _Ag = A + (size_t)(bm0 + ar) * K + _k0;                      \
        _Pragma("unroll")                                                         \
        for (int s = 0; s < 2; s++)                                               \
            cp_async16(&As[(buf)*A_STAGE + ar*ASTR + (ac + s)*4], _Ag + (ac + s)*4);\
        const float* _Bg = B + (size_t)(_k0 + br) * ldb + bn0;                    \
        _Pragma("unroll")                                                         \
        for (int s = 0; s < 4; s++)                                               \
            cp_async16(&Bs[(buf)*B_STAGE + br*BSTR + (bc + s*16)*4], _Bg + (bc + s*16)*4);\
    } while (0)

    STAGE_TILE(0, 0);
    asm volatile("cp.async.commit_group;");
    STAGE_TILE(1, 1);
    asm volatile("cp.async.commit_group;");

    for (int t = 0; t < T; t++) {
        const int buf = t & 3;
        if (t + 2 < T)
            STAGE_TILE(t + 2, (t + 2) & 3);
        asm volatile("cp.async.commit_group;");   /* uniform group count (may be empty) */
        asm volatile("cp.async.wait_group 2;");   /* group t complete */
        __syncthreads();                          /* single barrier per iteration */

        const uint32_t* Ab = (const uint32_t*)(As + buf * A_STAGE);
        const uint32_t* Bb = (const uint32_t*)(Bs + buf * B_STAGE);

        #pragma unroll
        for (int ks = 0; ks < 4; ks++) {
            const int kk = ks * 8;
            uint32_t a[4][4], b[4][2];
            #pragma unroll
            for (int i = 0; i < 4; i++) {
                const int mr = wm + i * 16 + g;
                a[i][0] = Ab[mr * ASTR + kk + t4];
                a[i][1] = Ab[(mr + 8) * ASTR + kk + t4];
                a[i][2] = Ab[mr * ASTR + kk + t4 + 4];
                a[i][3] = Ab[(mr + 8) * ASTR + kk + t4 + 4];
            }
            #pragma unroll
            for (int j = 0; j < 4; j++) {
                const int nc = wn + j * 8 + g;
                b[j][0] = Bb[(kk + t4) * BSTR + nc];
                b[j][1] = Bb[(kk + t4 + 4) * BSTR + nc];
            }
            #pragma unroll
            for (int i = 0; i < 4; i++)
                #pragma unroll
                for (int j = 0; j < 4; j++) {
                    asm volatile(
                        "mma.sync.aligned.m16n8k8.row.col.f32.tf32.tf32.f32 "
                        "{%0,%1,%2,%3}, {%4,%5,%6,%7}, {%8,%9}, {%0,%1,%2,%3};"
                        : "+f"(acc[i][j][0]), "+f"(acc[i][j][1]),
                          "+f"(acc[i][j][2]), "+f"(acc[i][j][3])
                        : "r"(a[i][0]), "r"(a[i][1]), "r"(a[i][2]), "r"(a[i][3]),
                          "r"(b[j][0]), "r"(b[j][1]));
                }
        }
    }
    #undef STAGE_TILE

    #pragma unroll
    for (int i = 0; i < 4; i++) {
        int row0 = bm0 + wm + i * 16 + g;
        #pragma unroll
        for (int j = 0; j < 4; j++) {
            int col = bn0 + wn + j * 8 + 2 * t4;
            *(float2*)(C + (size_t)row0 * ldc + col)       = make_float2(acc[i][j][0], acc[i][j][1]);
            *(float2*)(C + (size_t)(row0 + 8) * ldc + col) = make_float2(acc[i][j][2], acc[i][j][3]);
        }
    }
}

/* fused QKV: grid.x = 24 (16 Q cols + 4 K + 4 V), grid.y = 16 */
__global__ __launch_bounds__(512, 1) void qkv_gemm_kernel()
{
    extern __shared__ float sm[];
    const int bx = blockIdx.x;
    const int bm0 = blockIdx.y * GBM;
    if (bx < 16)
        gemm_body(g_hs, g_wq, g_q, QDIM, QDIM, HIDDEN, bm0, bx * GBN, sm);
    else if (bx < 20)
        gemm_body(g_hs, g_wk, g_k, KVDIM, KVDIM, HIDDEN, bm0, (bx - 16) * GBN, sm);
    else
        gemm_body(g_hs, g_wv, g_v, KVDIM, KVDIM, HIDDEN, bm0, (bx - 20) * GBN, sm);
}

__global__ __launch_bounds__(512, 1) void o_gemm_kernel(float* __restrict__ out)
{
    extern __shared__ float sm[];
    gemm_body(g_attn, g_wo, out, HIDDEN, HIDDEN, QDIM, blockIdx.y * GBM, blockIdx.x * GBN, sm);
}

/* ------------------------- RoPE (NeoX) ------------------------- */
__global__ void rope_kernel(float* x, const int* __restrict__ positions, int nheads)
{
    int idx = blockIdx.x * blockDim.x + threadIdx.x;
    int total = SEQ * nheads * (HD / 2);
    if (idx >= total) return;
    int i = idx & 63;
    int h = (idx >> 6) % nheads;
    int s = idx / (64 * nheads);
    float inv = powf(1000000.0f, -(float)i * (1.0f / 64.0f));
    float f = (float)positions[s] * inv;
    float c = cosf(f), sn = sinf(f);
    float* base = x + ((size_t)s * nheads + h) * HD;
    float x1 = base[i], x2 = base[i + 64];
    base[i]      = x1 * c - x2 * sn;
    base[i + 64] = x2 * c + x1 * sn;
}

/* ------------------------- Attention: bf16x3 tensor-core flash ------------------------- */
#define AQT 128
#define AKT 64
#define KPAD 68
#define VPAD 136

#define MMA_BF16(c, a0,a1,a2,a3, b0,b1)                                      \
    asm volatile("mma.sync.aligned.m16n8k16.row.col.f32.bf16.bf16.f32 "      \
        "{%0,%1,%2,%3}, {%4,%5,%6,%7}, {%8,%9}, {%0,%1,%2,%3};"              \
        : "+f"(c[0]), "+f"(c[1]), "+f"(c[2]), "+f"(c[3])                     \
        : "r"(a0), "r"(a1), "r"(a2), "r"(a3), "r"(b0), "r"(b1))

__device__ __forceinline__ void split2(float x, float y, uint32_t& hi, uint32_t& lo) {
    __nv_bfloat162 h = __float22bfloat162_rn(make_float2(x, y));
    float rx = x - __bfloat162float(h.x);
    float ry = y - __bfloat162float(h.y);
    __nv_bfloat162 l = __float22bfloat162_rn(make_float2(rx, ry));
    hi = *(uint32_t*)&h;
    lo = *(uint32_t*)&l;
}

__global__ __launch_bounds__(256, 1) void attn_mma_kernel(const float* __restrict__ sink)
{
    extern __shared__ uint32_t smw[];
    uint32_t* Qh = smw;
    uint32_t* Ql = Qh + AQT * KPAD;
    uint32_t* Kh = Ql + AQT * KPAD;
    uint32_t* Kl = Kh + AKT * KPAD;
    uint32_t* Vh = Kl + AKT * KPAD;
    uint32_t* Vl = Vh + (AKT/2) * VPAD;

    const int h   = blockIdx.y;
    const int q0  = blockIdx.x * AQT;
    const int kvh = h >> 2;
    const int tid = threadIdx.x;
    const int lane = tid & 31;
    const int wid  = tid >> 5;
    const int wrow = wid * 16;
    const int t4   = lane & 3;
    const int g    = lane >> 2;

    {
        const float* Qg = g_q + (size_t)q0 * QDIM + h * HD;
        #pragma unroll
        for (int it = 0; it < 16; it++) {
            int slot = tid + it * 256;
            int r = slot >> 5, d4 = slot & 31;
            float4 v = *(const float4*)(Qg + (size_t)r * QDIM + d4 * 4);
            uint32_t h01, l01, h23, l23;
            split2(v.x, v.y, h01, l01);
            split2(v.z, v.w, h23, l23);
            Qh[r * KPAD + d4 * 2]     = h01;
            Qh[r * KPAD + d4 * 2 + 1] = h23;
            Ql[r * KPAD + d4 * 2]     = l01;
            Ql[r * KPAD + d4 * 2 + 1] = l23;
        }
    }

    float o[16][4];
    #pragma unroll
    for (int i = 0; i < 16; i++)
        #pragma unroll
        for (int r = 0; r < 4; r++) o[i][r] = 0.f;
    float l0 = 0.f, l1 = 0.f;

    int jlo = q0 - (WINDOW - 1);
    if (jlo < 0) jlo = 0;
    int kt0 = (jlo / AKT) * AKT;

    const int qi0 = q0 + wrow + g;
    const int qi1 = qi0 + 8;

    for (int kt = kt0; kt < q0 + AQT; kt += AKT) {
        __syncthreads();
        {
            const float* Kg = g_k + (size_t)kt * KVDIM + kvh * HD;
            #pragma unroll
            for (int it = 0; it < 8; it++) {
                int slot = tid + it * 256;
                int r = slot >> 5, d4 = slot & 31;
                float4 v = *(const float4*)(Kg + (size_t)r * KVDIM + d4 * 4);
                uint32_t h01, l01, h23, l23;
                split2(v.x, v.y, h01, l01);
                split2(v.z, v.w, h23, l23);
                Kh[r * KPAD + d4 * 2]     = h01;
                Kh[r * KPAD + d4 * 2 + 1] = h23;
                Kl[r * KPAD + d4 * 2]     = l01;
                Kl[r * KPAD + d4 * 2 + 1] = l23;
            }
        }
        {
            const float* Vg = g_v + (size_t)kt * KVDIM + kvh * HD;
            #pragma unroll
            for (int it = 0; it < 4; it++) {
                int slot = tid + it * 256;
                int rp = slot >> 5, d4 = slot & 31;
                float4 v0 = *(const float4*)(Vg + (size_t)(2 * rp) * KVDIM + d4 * 4);
                float4 v1 = *(const float4*)(Vg + (size_t)(2 * rp + 1) * KVDIM + d4 * 4);
                const float* a = &v0.x;
                const float* b = &v1.x;
                #pragma unroll
                for (int jj = 0; jj < 4; jj++) {
                    uint32_t hi, lo;
                    split2(a[jj], b[jj], hi, lo);
                    Vh[rp * VPAD + d4 * 4 + jj] = hi;
                    Vl[rp * VPAD + d4 * 4 + jj] = lo;
                }
            }
        }
        __syncthreads();

        float s[8][4];
        #pragma unroll
        for (int nt = 0; nt < 8; nt++)
            #pragma unroll
            for (int r = 0; r < 4; r++) s[nt][r] = 0.f;

        #pragma unroll
        for (int kk = 0; kk < 8; kk++) {
            const int kw = kk * 8;
            uint32_t ah0 = Qh[(wrow + g)     * KPAD + kw + t4];
            uint32_t ah1 = Qh[(wrow + g + 8) * KPAD + kw + t4];
            uint32_t ah2 = Qh[(wrow + g)     * KPAD + kw + t4 + 4];
            uint32_t ah3 = Qh[(wrow + g + 8) * KPAD + kw + t4 + 4];
            uint32_t al0 = Ql[(wrow + g)     * KPAD + kw + t4];
            uint32_t al1 = Ql[(wrow + g + 8) * KPAD + kw + t4];
            uint32_t al2 = Ql[(wrow + g)     * KPAD + kw + t4 + 4];
            uint32_t al3 = Ql[(wrow + g + 8) * KPAD + kw + t4 + 4];
            #pragma unroll
            for (int nt = 0; nt < 8; nt++) {
                const int krow = nt * 8 + g;
                uint32_t bh0 = Kh[krow * KPAD + kw + t4];
                uint32_t bh1 = Kh[krow * KPAD + kw + t4 + 4];
                uint32_t bl0 = Kl[krow * KPAD + kw + t4];
                uint32_t bl1 = Kl[krow * KPAD + kw + t4 + 4];
                MMA_BF16(s[nt], ah0, ah1, ah2, ah3, bh0, bh1);
                MMA_BF16(s[nt], ah0, ah1, ah2, ah3, bl0, bl1);
                MMA_BF16(s[nt], al0, al1, al2, al3, bh0, bh1);
            }
        }

        #pragma unroll
        for (int nt = 0; nt < 8; nt++) {
            int c0 = kt + nt * 8 + 2 * t4;
            int c1 = c0 + 1;
            float p0 = (c0 <= qi0 && qi0 - c0 < WINDOW) ? __expf(s[nt][0] * SCALING) : 0.f;
            float p1 = (c1 <= qi0 && qi0 - c1 < WINDOW) ? __expf(s[nt][1] * SCALING) : 0.f;
            float p2 = (c0 <= qi1 && qi1 - c0 < WINDOW) ? __expf(s[nt][2] * SCALING) : 0.f;
            float p3 = (c1 <= qi1 && qi1 - c1 < WINDOW) ? __expf(s[nt][3] * SCALING) : 0.f;
            l0 += p0 + p1;
            l1 += p2 + p3;
            s[nt][0] = p0; s[nt][1] = p1; s[nt][2] = p2; s[nt][3] = p3;
        }

        #pragma unroll
        for (int ks = 0; ks < 4; ks++) {
            uint32_t ah0, al0, ah1, al1, ah2, al2, ah3, al3;
            split2(s[2*ks][0],   s[2*ks][1],   ah0, al0);
            split2(s[2*ks][2],   s[2*ks][3],   ah1, al1);
            split2(s[2*ks+1][0], s[2*ks+1][1], ah2, al2);
            split2(s[2*ks+1][2], s[2*ks+1][3], ah3, al3);
            #pragma unroll
            for (int nt = 0; nt < 16; nt++) {
                uint32_t bh0 = Vh[(ks * 8 + t4)     * VPAD + nt * 8 + g];
                uint32_t bh1 = Vh[(ks * 8 + t4 + 4) * VPAD + nt * 8 + g];
                uint32_t bl0 = Vl[(ks * 8 + t4)     * VPAD + nt * 8 + g];
                uint32_t bl1 = Vl[(ks * 8 + t4 + 4) * VPAD + nt * 8 + g];
                MMA_BF16(o[nt], ah0, ah1, ah2, ah3, bh0, bh1);
                MMA_BF16(o[nt], ah0, ah1, ah2, ah3, bl0, bl1);
                MMA_BF16(o[nt], al0, al1, al2, al3, bh0, bh1);
            }
        }
    }

    l0 += __shfl_xor_sync(0xffffffffu, l0, 1);
    l0 += __shfl_xor_sync(0xffffffffu, l0, 2);
    l1 += __shfl_xor_sync(0xffffffffu, l1, 1);
    l1 += __shfl_xor_sync(0xffffffffu, l1, 2);
    float sk = __expf(sink[h]);
    float inv0 = 1.0f / (l0 + sk);
    float inv1 = 1.0f / (l1 + sk);

    /* store tf32-rounded so the O-projection GEMM can consume raw bits */
    float* out0 = g_attn + (size_t)qi0 * QDIM + h * HD;
    float* out1 = g_attn + (size_t)qi1 * QDIM + h * HD;
    #pragma unroll
    for (int nt = 0; nt < 16; nt++) {
        int d = nt * 8 + 2 * t4;
        *(float2*)(out0 + d) = make_float2(roundtf(o[nt][0] * inv0), roundtf(o[nt][1] * inv0));
        *(float2*)(out1 + d) = make_float2(roundtf(o[nt][2] * inv1), roundtf(o[nt][3] * inv1));
    }
}

/* ------------------------- launch ------------------------- */
extern "C" void kernel_launch(void* const* d_in, const int* in_sizes, int n_in,
                              void* d_out, int out_size)
{
    const float* hs   = (const float*)d_in[0];
    const int*   pos  = (const int*)d_in[1];
    const float* wq   = (const float*)d_in[2];
    const float* wk   = (const float*)d_in[3];
    const float* wv   = (const float*)d_in[4];
    const float* wo   = (const float*)d_in[5];
    const float* sink = (const float*)d_in[6];
    float* out = (float*)d_out;

    float *q_ptr, *k_ptr, *hs_ptr, *wq_ptr, *wk_ptr, *wv_ptr, *wo_ptr;
    cudaGetSymbolAddress((void**)&q_ptr, g_q);
    cudaGetSymbolAddress((void**)&k_ptr, g_k);
    cudaGetSymbolAddress((void**)&hs_ptr, g_hs);
    cudaGetSymbolAddress((void**)&wq_ptr, g_wq);
    cudaGetSymbolAddress((void**)&wk_ptr, g_wk);
    cudaGetSymbolAddress((void**)&wv_ptr, g_wv);
    cudaGetSymbolAddress((void**)&wo_ptr, g_wo);

    cudaFuncSetAttribute(qkv_gemm_kernel, cudaFuncAttributeMaxDynamicSharedMemorySize, GEMM_SMEM);
    cudaFuncSetAttribute(o_gemm_kernel,  cudaFuncAttributeMaxDynamicSharedMemorySize, GEMM_SMEM);

    /* tf32 pre-rounding of GEMM inputs */
    round_tf32_kernel<<<(SEQ*HIDDEN/4 + 255)/256, 256>>>(hs, hs_ptr, SEQ*HIDDEN/4);
    round_tf32_kernel<<<(HIDDEN*QDIM/4 + 255)/256, 256>>>(wq, wq_ptr, HIDDEN*QDIM/4);
    round_tf32_kernel<<<(HIDDEN*KVDIM/4 + 255)/256, 256>>>(wk, wk_ptr, HIDDEN*KVDIM/4);
    round_tf32_kernel<<<(HIDDEN*KVDIM/4 + 255)/256, 256>>>(wv, wv_ptr, HIDDEN*KVDIM/4);
    round_tf32_kernel<<<(QDIM*HIDDEN/4 + 255)/256, 256>>>(wo, wo_ptr, QDIM*HIDDEN/4);

    /* fused QKV projection (512 threads, 4 warps/SMSP) */
    qkv_gemm_kernel<<<dim3(24, SEQ / GBM), 512, GEMM_SMEM>>>();

    /* RoPE */
    {
        int tq = SEQ * NQH * (HD / 2);
        rope_kernel<<<(tq + 255) / 256, 256>>>(q_ptr, pos, NQH);
        int tk = SEQ * NKVH * (HD / 2);
        rope_kernel<<<(tk + 255) / 256, 256>>>(k_ptr, pos, NKVH);
    }

    /* attention (bf16x3 tensor cores) */
    {
        int smem_words = 2 * AQT * KPAD + 2 * AKT * KPAD + 2 * (AKT/2) * VPAD;
        int smem = smem_words * 4;
        cudaFuncSetAttribute(attn_mma_kernel, cudaFuncAttributeMaxDynamicSharedMemorySize, smem);
        attn_mma_kernel<<<dim3(SEQ / AQT, NQH), 256, smem>>>(sink);
    }

    /* output projection */
    o_gemm_kernel<<<dim3(HIDDEN / GBN, SEQ / GBM), 512, GEMM_SMEM>>>(out);
}

// round 16
// speedup vs baseline: 1.0085x; 1.0071x over previous
#include <cuda_runtime.h>
#include <cuda_bf16.h>
#include <math.h>
#include <stdint.h>

#define SEQ 2048
#define HIDDEN 4096
#define NQH 32
#define NKVH 8
#define HD 128
#define QDIM (NQH*HD)      /* 4096 */
#define KVDIM (NKVH*HD)    /* 1024 */
#define WINDOW 1024
#define SCALING 0.08838834764831845f

/* scratch (allocation-free rule: __device__ globals) */
__device__ float g_q[SEQ*QDIM];
__device__ float g_k[SEQ*KVDIM];
__device__ float g_v[SEQ*KVDIM];
__device__ float g_attn[SEQ*QDIM];
/* tf32-pre-rounded GEMM operands */
__device__ float g_hs[SEQ*HIDDEN];
__device__ float g_wq[HIDDEN*QDIM];
__device__ float g_wk[HIDDEN*KVDIM];
__device__ float g_wv[HIDDEN*KVDIM];
__device__ float g_wo[QDIM*HIDDEN];
/* pre-split K (hi/lo bf16, mirrors g_k layout) and pre-packed V (j-pair bf16x2 words) */
__device__ __nv_bfloat16 g_kh[SEQ*KVDIM], g_kl[SEQ*KVDIM];
__device__ uint32_t g_vph[(SEQ/2)*KVDIM], g_vpl[(SEQ/2)*KVDIM];

__device__ __forceinline__ float roundtf(float x) {
    float r;
    asm("cvt.rna.tf32.f32 %0, %1;" : "=f"(r) : "f"(x));
    return r;
}

/* elementwise tf32 rounding pass */
__global__ void round_tf32_kernel(const float* __restrict__ in, float* __restrict__ out, int n4)
{
    int i = blockIdx.x * blockDim.x + threadIdx.x;
    if (i >= n4) return;
    float4 v = ((const float4*)in)[i];
    v.x = roundtf(v.x); v.y = roundtf(v.y);
    v.z = roundtf(v.z); v.w = roundtf(v.w);
    ((float4*)out)[i] = v;
}

__device__ __forceinline__ void split2(float x, float y, uint32_t& hi, uint32_t& lo) {
    __nv_bfloat162 h = __float22bfloat162_rn(make_float2(x, y));
    float rx = x - __bfloat162float(h.x);
    float ry = y - __bfloat162float(h.y);
    __nv_bfloat162 l = __float22bfloat162_rn(make_float2(rx, ry));
    hi = *(uint32_t*)&h;
    lo = *(uint32_t*)&l;
}

/* K split: fp32 -> hi/lo bf16 pairs (consecutive d elements packed per word) */
__global__ void split_k_kernel(int n2)
{
    int i = blockIdx.x * blockDim.x + threadIdx.x;
    if (i >= n2) return;
    float2 v = ((const float2*)g_k)[i];
    uint32_t hi, lo;
    split2(v.x, v.y, hi, lo);
    ((uint32_t*)g_kh)[i] = hi;
    ((uint32_t*)g_kl)[i] = lo;
}

/* V pack: word [p][x] = bf16x2( v[2p][x], v[2p+1][x] ), hi and lo splits */
__global__ void pack_v_kernel(int n)   /* n = (SEQ/2)*KVDIM */
{
    int i = blockIdx.x * blockDim.x + threadIdx.x;
    if (i >= n) return;
    int p = i / KVDIM, x = i % KVDIM;
    float v0 = g_v[(size_t)(2 * p) * KVDIM + x];
    float v1 = g_v[(size_t)(2 * p + 1) * KVDIM + x];
    uint32_t hi, lo;
    split2(v0, v1, hi, lo);
    g_vph[i] = hi;
    g_vpl[i] = lo;
}

/* ------- TF32 GEMM: 128x256 CTA, 16 warps (64x32 each), 4-stage cp.async (R15) ------- */

#define GBM 128
#define GBN 256
#define GBK 32
#define ASTR 36
#define BSTR 264
#define A_STAGE (GBM*ASTR)
#define B_STAGE (GBK*BSTR)
#define STG 4
#define GEMM_SMEM (STG*(A_STAGE+B_STAGE)*4)   /* 208896 B */

__device__ __forceinline__ void cp_async16(const void* smem_gen, const void* gptr) {
    uint32_t s = (uint32_t)__cvta_generic_to_shared(smem_gen);
    asm volatile("cp.async.cg.shared.global [%0], [%1], 16;" :: "r"(s), "l"(gptr));
}

__device__ __forceinline__ void gemm_body(
    const float* __restrict__ A, const float* __restrict__ B, float* __restrict__ C,
    int ldb, int ldc, int K, int bm0, int bn0, float* sm)
{
    float* As = sm;
    float* Bs = sm + STG * A_STAGE;

    const int tid  = threadIdx.x;
    const int lane = tid & 31;
    const int wid  = tid >> 5;
    const int wm   = (wid & 1) * 64;
    const int wn   = (wid >> 1) * 32;
    const int t4   = lane & 3;
    const int g    = lane >> 2;

    float acc[4][4][4];
    #pragma unroll
    for (int i = 0; i < 4; i++)
        #pragma unroll
        for (int j = 0; j < 4; j++)
            #pragma unroll
            for (int r = 0; r < 4; r++) acc[i][j][r] = 0.f;

    const int ar = tid >> 2;
    const int ac = (tid & 3) * 2;
    const int br = tid >> 4;
    const int bc = tid & 15;

    const int T = K / GBK;

    #define STAGE_TILE(ti, buf) do {                                              \
        const int _k0 = (ti) * GBK;                                               \
        const float* _Ag = A + (size_t)(bm0 + ar) * K + _k0;                      \
        _Pragma("unroll")                                                         \
        for (int s = 0; s < 2; s++)                                               \
            cp_async16(&As[(buf)*A_STAGE + ar*ASTR + (ac + s)*4], _Ag + (ac + s)*4);\
        const float* _Bg = B + (size_t)(_k0 + br) * ldb + bn0;                    \
        _Pragma("unroll")                                                         \
        for (int s = 0; s < 4; s++)                                               \
            cp_async16(&Bs[(buf)*B_STAGE + br*BSTR + (bc + s*16)*4], _Bg + (bc + s*16)*4);\
    } while (0)

    STAGE_TILE(0, 0);
    asm volatile("cp.async.commit_group;");
    STAGE_TILE(1, 1);
    asm volatile("cp.async.commit_group;");

    for (int t = 0; t < T; t++) {
        const int buf = t & 3;
        if (t + 2 < T)
            STAGE_TILE(t + 2, (t + 2) & 3);
        asm volatile("cp.async.commit_group;");
        asm volatile("cp.async.wait_group 2;");
        __syncthreads();

        const uint32_t* Ab = (const uint32_t*)(As + buf * A_STAGE);
        const uint32_t* Bb = (const uint32_t*)(Bs + buf * B_STAGE);

        #pragma unroll
        for (int ks = 0; ks < 4; ks++) {
            const int kk = ks * 8;
            uint32_t a[4][4], b[4][2];
            #pragma unroll
            for (int i = 0; i < 4; i++) {
                const int mr = wm + i * 16 + g;
                a[i][0] = Ab[mr * ASTR + kk + t4];
                a[i][1] = Ab[(mr + 8) * ASTR + kk + t4];
                a[i][2] = Ab[mr * ASTR + kk + t4 + 4];
                a[i][3] = Ab[(mr + 8) * ASTR + kk + t4 + 4];
            }
            #pragma unroll
            for (int j = 0; j < 4; j++) {
                const int nc = wn + j * 8 + g;
                b[j][0] = Bb[(kk + t4) * BSTR + nc];
                b[j][1] = Bb[(kk + t4 + 4) * BSTR + nc];
            }
            #pragma unroll
            for (int i = 0; i < 4; i++)
                #pragma unroll
                for (int j = 0; j < 4; j++) {
                    asm volatile(
                        "mma.sync.aligned.m16n8k8.row.col.f32.tf32.tf32.f32 "
                        "{%0,%1,%2,%3}, {%4,%5,%6,%7}, {%8,%9}, {%0,%1,%2,%3};"
                        : "+f"(acc[i][j][0]), "+f"(acc[i][j][1]),
                          "+f"(acc[i][j][2]), "+f"(acc[i][j][3])
                        : "r"(a[i][0]), "r"(a[i][1]), "r"(a[i][2]), "r"(a[i][3]),
                          "r"(b[j][0]), "r"(b[j][1]));
                }
        }
    }
    #undef STAGE_TILE

    #pragma unroll
    for (int i = 0; i < 4; i++) {
        int row0 = bm0 + wm + i * 16 + g;
        #pragma unroll
        for (int j = 0; j < 4; j++) {
            int col = bn0 + wn + j * 8 + 2 * t4;
            *(float2*)(C + (size_t)row0 * ldc + col)       = make_float2(acc[i][j][0], acc[i][j][1]);
            *(float2*)(C + (size_t)(row0 + 8) * ldc + col) = make_float2(acc[i][j][2], acc[i][j][3]);
        }
    }
}

__global__ __launch_bounds__(512, 1) void qkv_gemm_kernel()
{
    extern __shared__ float sm[];
    const int bx = blockIdx.x;
    const int bm0 = blockIdx.y * GBM;
    if (bx < 16)
        gemm_body(g_hs, g_wq, g_q, QDIM, QDIM, HIDDEN, bm0, bx * GBN, sm);
    else if (bx < 20)
        gemm_body(g_hs, g_wk, g_k, KVDIM, KVDIM, HIDDEN, bm0, (bx - 16) * GBN, sm);
    else
        gemm_body(g_hs, g_wv, g_v, KVDIM, KVDIM, HIDDEN, bm0, (bx - 20) * GBN, sm);
}

__global__ __launch_bounds__(512, 1) void o_gemm_kernel(float* __restrict__ out)
{
    extern __shared__ float sm[];
    gemm_body(g_attn, g_wo, out, HIDDEN, HIDDEN, QDIM, blockIdx.y * GBM, blockIdx.x * GBN, sm);
}

/* ------------------------- RoPE (NeoX) ------------------------- */
__global__ void rope_kernel(float* x, const int* __restrict__ positions, int nheads)
{
    int idx = blockIdx.x * blockDim.x + threadIdx.x;
    int total = SEQ * nheads * (HD / 2);
    if (idx >= total) return;
    int i = idx & 63;
    int h = (idx >> 6) % nheads;
    int s = idx / (64 * nheads);
    float inv = powf(1000000.0f, -(float)i * (1.0f / 64.0f));
    float f = (float)positions[s] * inv;
    float c = cosf(f), sn = sinf(f);
    float* base = x + ((size_t)s * nheads + h) * HD;
    float x1 = base[i], x2 = base[i + 64];
    base[i]      = x1 * c - x2 * sn;
    base[i + 64] = x2 * c + x1 * sn;
}

/* --------- Attention: bf16x3 mma flash, pre-split K/V + 2-stage cp.async pipeline ------ */
#define AQT 128
#define AKT 64
#define KPAD 68
#define VPAD 136
/* smem word layout: Qh[128*68] Ql[128*68] | stage0{Kh[4352] Kl[4352] Vh[4352] Vl[4352]} stage1{...} */
#define QW   (AQT*KPAD)            /* 8704 words per Q array */
#define KVW  4352                  /* words per K or V array per stage */
#define STGW (4*KVW)               /* 17408 words per stage */
#define ATT_SMEM ((2*QW + 2*STGW)*4)   /* 208896 B */

#define MMA_BF16(c, a0,a1,a2,a3, b0,b1)                                      \
    asm volatile("mma.sync.aligned.m16n8k16.row.col.f32.bf16.bf16.f32 "      \
        "{%0,%1,%2,%3}, {%4,%5,%6,%7}, {%8,%9}, {%0,%1,%2,%3};"              \
        : "+f"(c[0]), "+f"(c[1]), "+f"(c[2]), "+f"(c[3])                     \
        : "r"(a0), "r"(a1), "r"(a2), "r"(a3), "r"(b0), "r"(b1))

__global__ __launch_bounds__(256, 1) void attn_mma_kernel(const float* __restrict__ sink)
{
    extern __shared__ uint32_t smw[];
    uint32_t* Qh = smw;
    uint32_t* Ql = Qh + QW;

    const int h   = blockIdx.y;
    const int q0  = blockIdx.x * AQT;
    const int kvh = h >> 2;
    const int tid = threadIdx.x;
    const int lane = tid & 31;
    const int wid  = tid >> 5;
    const int wrow = wid * 16;
    const int t4   = lane & 3;
    const int g    = lane >> 2;

    /* Q tile load + split (once) */
    {
        const float* Qg = g_q + (size_t)q0 * QDIM + h * HD;
        #pragma unroll
        for (int it = 0; it < 16; it++) {
            int slot = tid + it * 256;
            int r = slot >> 5, d4 = slot & 31;
            float4 v = *(const float4*)(Qg + (size_t)r * QDIM + d4 * 4);
            uint32_t h01, l01, h23, l23;
            split2(v.x, v.y, h01, l01);
            split2(v.z, v.w, h23, l23);
            Qh[r * KPAD + d4 * 2]     = h01;
            Qh[r * KPAD + d4 * 2 + 1] = h23;
            Ql[r * KPAD + d4 * 2]     = l01;
            Ql[r * KPAD + d4 * 2 + 1] = l23;
        }
    }

    float o[16][4];
    #pragma unroll
    for (int i = 0; i < 16; i++)
        #pragma unroll
        for (int r = 0; r < 4; r++) o[i][r] = 0.f;
    float l0 = 0.f, l1 = 0.f;

    int jlo = q0 - (WINDOW - 1);
    if (jlo < 0) jlo = 0;
    const int kt0 = (jlo / AKT) * AKT;
    const int ktend = q0 + AQT;

    const int qi0 = q0 + wrow + g;
    const int qi1 = qi0 + 8;

    /* cp.async staging of one K/V tile (hi/lo each): 4096 chunks of 16B, 16/thread */
    #define ATT_STAGE(kt, sb) do {                                                      \
        uint32_t* _s = smw + 2 * QW + (sb) * STGW;                                      \
        _Pragma("unroll")                                                               \
        for (int s = 0; s < 8; s++) {            /* K: 2048 chunks */                   \
            int c = tid + s * 256;                                                      \
            int arr = c >> 10, idx = c & 1023;                                          \
            int row = idx >> 4, ch = idx & 15;                                          \
            const __nv_bfloat16* src = (arr ? g_kl : g_kh)                              \
                + (size_t)((kt) + row) * KVDIM + kvh * HD + ch * 8;                     \
            cp_async16(_s + arr * KVW + row * KPAD + ch * 4, src);                      \
        }                                                                               \
        _Pragma("unroll")                                                               \
        for (int s = 0; s < 8; s++) {            /* V: 2048 chunks */                   \
            int c = tid + s * 256;                                                      \
            int arr = c >> 10, idx = c & 1023;                                          \
            int rp = idx >> 5, ch = idx & 31;                                           \
            const uint32_t* src = (arr ? g_vpl : g_vph)                                 \
                + (size_t)((kt) / 2 + rp) * KVDIM + kvh * HD + ch * 4;                  \
            cp_async16(_s + 2 * KVW + arr * KVW + rp * VPAD + ch * 4, src);             \
        }                                                                               \
    } while (0)

    ATT_STAGE(kt0, 0);
    asm volatile("cp.async.commit_group;");

    int it = 0;
    for (int kt = kt0; kt < ktend; kt += AKT, it++) {
        __syncthreads();   /* prior compute done before overwriting buf^1 */
        if (kt + AKT < ktend)
            ATT_STAGE(kt + AKT, (it + 1) & 1);
        asm volatile("cp.async.commit_group;");
        asm volatile("cp.async.wait_group 1;");   /* tile `it` complete */
        __syncthreads();

        const uint32_t* Kh = smw + 2 * QW + (it & 1) * STGW;
        const uint32_t* Kl = Kh + KVW;
        const uint32_t* Vh = Kh + 2 * KVW;
        const uint32_t* Vl = Kh + 3 * KVW;

        float s[8][4];
        #pragma unroll
        for (int nt = 0; nt < 8; nt++)
            #pragma unroll
            for (int r = 0; r < 4; r++) s[nt][r] = 0.f;

        #pragma unroll
        for (int kk = 0; kk < 8; kk++) {
            const int kw = kk * 8;
            uint32_t ah0 = Qh[(wrow + g)     * KPAD + kw + t4];
            uint32_t ah1 = Qh[(wrow + g + 8) * KPAD + kw + t4];
            uint32_t ah2 = Qh[(wrow + g)     * KPAD + kw + t4 + 4];
            uint32_t ah3 = Qh[(wrow + g + 8) * KPAD + kw + t4 + 4];
            uint32_t al0 = Ql[(wrow + g)     * KPAD + kw + t4];
            uint32_t al1 = Ql[(wrow + g + 8) * KPAD + kw + t4];
            uint32_t al2 = Ql[(wrow + g)     * KPAD + kw + t4 + 4];
            uint32_t al3 = Ql[(wrow + g + 8) * KPAD + kw + t4 + 4];
            #pragma unroll
            for (int nt = 0; nt < 8; nt++) {
                const int krow = nt * 8 + g;
                uint32_t bh0 = Kh[krow * KPAD + kw + t4];
                uint32_t bh1 = Kh[krow * KPAD + kw + t4 + 4];
                uint32_t bl0 = Kl[krow * KPAD + kw + t4];
                uint32_t bl1 = Kl[krow * KPAD + kw + t4 + 4];
                MMA_BF16(s[nt], ah0, ah1, ah2, ah3, bh0, bh1);
                MMA_BF16(s[nt], ah0, ah1, ah2, ah3, bl0, bl1);
                MMA_BF16(s[nt], al0, al1, al2, al3, bh0, bh1);
            }
        }

        #pragma unroll
        for (int nt = 0; nt < 8; nt++) {
            int c0 = kt + nt * 8 + 2 * t4;
            int c1 = c0 + 1;
            float p0 = (c0 <= qi0 && qi0 - c0 < WINDOW) ? __expf(s[nt][0] * SCALING) : 0.f;
            float p1 = (c1 <= qi0 && qi0 - c1 < WINDOW) ? __expf(s[nt][1] * SCALING) : 0.f;
            float p2 = (c0 <= qi1 && qi1 - c0 < WINDOW) ? __expf(s[nt][2] * SCALING) : 0.f;
            float p3 = (c1 <= qi1 && qi1 - c1 < WINDOW) ? __expf(s[nt][3] * SCALING) : 0.f;
            l0 += p0 + p1;
            l1 += p2 + p3;
            s[nt][0] = p0; s[nt][1] = p1; s[nt][2] = p2; s[nt][3] = p3;
        }

        #pragma unroll
        for (int ks = 0; ks < 4; ks++) {
            uint32_t ah0, al0, ah1, al1, ah2, al2, ah3, al3;
            split2(s[2*ks][0],   s[2*ks][1],   ah0, al0);
            split2(s[2*ks][2],   s[2*ks][3],   ah1, al1);
            split2(s[2*ks+1][0], s[2*ks+1][1], ah2, al2);
            split2(s[2*ks+1][2], s[2*ks+1][3], ah3, al3);
            #pragma unroll
            for (int nt = 0; nt < 16; nt++) {
                uint32_t bh0 = Vh[(ks * 8 + t4)     * VPAD + nt * 8 + g];
                uint32_t bh1 = Vh[(ks * 8 + t4 + 4) * VPAD + nt * 8 + g];
                uint32_t bl0 = Vl[(ks * 8 + t4)     * VPAD + nt * 8 + g];
                uint32_t bl1 = Vl[(ks * 8 + t4 + 4) * VPAD + nt * 8 + g];
                MMA_BF16(o[nt], ah0, ah1, ah2, ah3, bh0, bh1);
                MMA_BF16(o[nt], ah0, ah1, ah2, ah3, bl0, bl1);
                MMA_BF16(o[nt], al0, al1, al2, al3, bh0, bh1);
            }
        }
    }
    #undef ATT_STAGE

    l0 += __shfl_xor_sync(0xffffffffu, l0, 1);
    l0 += __shfl_xor_sync(0xffffffffu, l0, 2);
    l1 += __shfl_xor_sync(0xffffffffu, l1, 1);
    l1 += __shfl_xor_sync(0xffffffffu, l1, 2);
    float sk = __expf(sink[h]);
    float inv0 = 1.0f / (l0 + sk);
    float inv1 = 1.0f / (l1 + sk);

    /* store tf32-rounded so the O-projection GEMM can consume raw bits */
    float* out0 = g_attn + (size_t)qi0 * QDIM + h * HD;
    float* out1 = g_attn + (size_t)qi1 * QDIM + h * HD;
    #pragma unroll
    for (int nt = 0; nt < 16; nt++) {
        int d = nt * 8 + 2 * t4;
        *(float2*)(out0 + d) = make_float2(roundtf(o[nt][0] * inv0), roundtf(o[nt][1] * inv0));
        *(float2*)(out1 + d) = make_float2(roundtf(o[nt][2] * inv1), roundtf(o[nt][3] * inv1));
    }
}

/* ------------------------- launch ------------------------- */
extern "C" void kernel_launch(void* const* d_in, const int* in_sizes, int n_in,
                              void* d_out, int out_size)
{
    const float* hs   = (const float*)d_in[0];
    const int*   pos  = (const int*)d_in[1];
    const float* wq   = (const float*)d_in[2];
    const float* wk   = (const float*)d_in[3];
    const float* wv   = (const float*)d_in[4];
    const float* wo   = (const float*)d_in[5];
    const float* sink = (const float*)d_in[6];
    float* out = (float*)d_out;

    float *q_ptr, *k_ptr, *hs_ptr, *wq_ptr, *wk_ptr, *wv_ptr, *wo_ptr;
    cudaGetSymbolAddress((void**)&q_ptr, g_q);
    cudaGetSymbolAddress((void**)&k_ptr, g_k);
    cudaGetSymbolAddress((void**)&hs_ptr, g_hs);
    cudaGetSymbolAddress((void**)&wq_ptr, g_wq);
    cudaGetSymbolAddress((void**)&wk_ptr, g_wk);
    cudaGetSymbolAddress((void**)&wv_ptr, g_wv);
    cudaGetSymbolAddress((void**)&wo_ptr, g_wo);

    cudaFuncSetAttribute(qkv_gemm_kernel, cudaFuncAttributeMaxDynamicSharedMemorySize, GEMM_SMEM);
    cudaFuncSetAttribute(o_gemm_kernel,  cudaFuncAttributeMaxDynamicSharedMemorySize, GEMM_SMEM);
    cudaFuncSetAttribute(attn_mma_kernel, cudaFuncAttributeMaxDynamicSharedMemorySize, ATT_SMEM);

    /* tf32 pre-rounding of GEMM inputs */
    round_tf32_kernel<<<(SEQ*HIDDEN/4 + 255)/256, 256>>>(hs, hs_ptr, SEQ*HIDDEN/4);
    round_tf32_kernel<<<(HIDDEN*QDIM/4 + 255)/256, 256>>>(wq, wq_ptr, HIDDEN*QDIM/4);
    round_tf32_kernel<<<(HIDDEN*KVDIM/4 + 255)/256, 256>>>(wk, wk_ptr, HIDDEN*KVDIM/4);
    round_tf32_kernel<<<(HIDDEN*KVDIM/4 + 255)/256, 256>>>(wv, wv_ptr, HIDDEN*KVDIM/4);
    round_tf32_kernel<<<(QDIM*HIDDEN/4 + 255)/256, 256>>>(wo, wo_ptr, QDIM*HIDDEN/4);

    /* fused QKV projection */
    qkv_gemm_kernel<<<dim3(24, SEQ / GBM), 512, GEMM_SMEM>>>();

    /* V pack can start as soon as QKV is done (independent of rope) */
    pack_v_kernel<<<((SEQ/2)*KVDIM + 255)/256, 256>>>((SEQ/2)*KVDIM);

    /* RoPE */
    {
        int tq = SEQ * NQH * (HD / 2);
        rope_kernel<<<(tq + 255) / 256, 256>>>(q_ptr, pos, NQH);
        int tk = SEQ * NKVH * (HD / 2);
        rope_kernel<<<(tk + 255) / 256, 256>>>(k_ptr, pos, NKVH);
    }

    /* K split (after rope) */
    split_k_kernel<<<(SEQ*KVDIM/2 + 255)/256, 256>>>(SEQ*KVDIM/2);

    /* attention (bf16x3 tensor cores, pipelined pre-split K/V) */
    attn_mma_kernel<<<dim3(SEQ / AQT, NQH), 256, ATT_SMEM>>>(sink);

    /* output projection */
    o_gemm_kernel<<<dim3(HIDDEN / GBN, SEQ / GBM), 512, GEMM_SMEM>>>(out);
}

// round 17
// speedup vs baseline: 1.0227x; 1.0141x over previous
#include <cuda_runtime.h>
#include <cuda_bf16.h>
#include <math.h>
#include <stdint.h>

#define SEQ 2048
#define HIDDEN 4096
#define NQH 32
#define NKVH 8
#define HD 128
#define QDIM (NQH*HD)      /* 4096 */
#define KVDIM (NKVH*HD)    /* 1024 */
#define WINDOW 1024
#define SCALING 0.08838834764831845f

/* scratch (allocation-free rule: __device__ globals) */
__device__ float g_q[SEQ*QDIM];
__device__ float g_k[SEQ*KVDIM];
__device__ float g_v[SEQ*KVDIM];
__device__ float g_attn[SEQ*QDIM];
/* tf32-pre-rounded GEMM operands */
__device__ float g_hs[SEQ*HIDDEN];
__device__ float g_wq[HIDDEN*QDIM];
__device__ float g_wk[HIDDEN*KVDIM];
__device__ float g_wv[HIDDEN*KVDIM];
__device__ float g_wo[QDIM*HIDDEN];
/* pre-split K (hi/lo bf16) and pre-packed V (j-pair bf16x2 words) */
__device__ __nv_bfloat16 g_kh[SEQ*KVDIM], g_kl[SEQ*KVDIM];
__device__ uint32_t g_vph[(SEQ/2)*KVDIM], g_vpl[(SEQ/2)*KVDIM];

__device__ __forceinline__ float roundtf(float x) {
    float r;
    asm("cvt.rna.tf32.f32 %0, %1;" : "=f"(r) : "f"(x));
    return r;
}

__device__ __forceinline__ void split2(float x, float y, uint32_t& hi, uint32_t& lo) {
    __nv_bfloat162 h = __float22bfloat162_rn(make_float2(x, y));
    float rx = x - __bfloat162float(h.x);
    float ry = y - __bfloat162float(h.y);
    __nv_bfloat162 l = __float22bfloat162_rn(make_float2(rx, ry));
    hi = *(uint32_t*)&h;
    lo = *(uint32_t*)&l;
}

/* ---------- merged tf32 rounding pass over all 5 GEMM operands (one launch) ---------- */
/* float4 blocks: hs 8192 | wq 16384 | wk 4096 | wv 4096 | wo 16384  = 49152 blocks */
#define RB_HS 8192
#define RB_WQ 16384
#define RB_WK 4096
#define RB_WV 4096
#define RB_WO 16384

__global__ __launch_bounds__(256) void round_all_kernel(
    const float* __restrict__ hs, const float* __restrict__ wq,
    const float* __restrict__ wk, const float* __restrict__ wv,
    const float* __restrict__ wo)
{
    int b = blockIdx.x;
    const float* src;
    float* dst;
    int rel;
    if (b < RB_HS)                      { rel = b;                          src = hs; dst = g_hs; }
    else if (b < RB_HS+RB_WQ)           { rel = b - RB_HS;                  src = wq; dst = g_wq; }
    else if (b < RB_HS+RB_WQ+RB_WK)     { rel = b - RB_HS-RB_WQ;            src = wk; dst = g_wk; }
    else if (b < RB_HS+RB_WQ+RB_WK+RB_WV){ rel = b - RB_HS-RB_WQ-RB_WK;     src = wv; dst = g_wv; }
    else                                { rel = b - RB_HS-RB_WQ-RB_WK-RB_WV; src = wo; dst = g_wo; }
    int i = rel * 256 + threadIdx.x;
    float4 v = ((const float4*)src)[i];
    v.x = roundtf(v.x); v.y = roundtf(v.y);
    v.z = roundtf(v.z); v.w = roundtf(v.w);
    ((float4*)dst)[i] = v;
}

/* ---------- merged prep: rope_q | rope_k+split | pack_v (one launch) ---------- */
#define RQ_BLOCKS 16384   /* SEQ*NQH*64 / 256  */
#define RK_BLOCKS 4096    /* SEQ*NKVH*64 / 256 */
#define PV_BLOCKS 4096    /* (SEQ/2)*KVDIM / 256 */

__global__ __launch_bounds__(256) void prep_kernel(const int* __restrict__ positions)
{
    const int b = blockIdx.x;
    const int t = threadIdx.x;
    if (b < RQ_BLOCKS) {
        /* rope on Q, in place; inv_freq via smem table (identical powf values) */
        __shared__ float invf[64];
        if (t < 64) invf[t] = powf(1000000.0f, -(float)t * (1.0f / 64.0f));
        __syncthreads();
        int idx = b * 256 + t;
        int i = idx & 63;
        int h = (idx >> 6) % NQH;
        int s = idx / (64 * NQH);
        float f = (float)positions[s] * invf[i];
        float c = cosf(f), sn = sinf(f);
        float* base = g_q + ((size_t)s * NQH + h) * HD;
        float x1 = base[i], x2 = base[i + 64];
        base[i]      = x1 * c - x2 * sn;
        base[i + 64] = x2 * c + x1 * sn;
    } else if (b < RQ_BLOCKS + RK_BLOCKS) {
        /* rope on K fused with hi/lo bf16 split (g_k itself no longer consumed) */
        const int bb = b - RQ_BLOCKS;
        __shared__ float invf[64];
        __shared__ float rows[4][128];
        if (t < 64) invf[t] = powf(1000000.0f, -(float)t * (1.0f / 64.0f));
        __syncthreads();
        const int i = t & 63;
        const int r = t >> 6;            /* 0..3 */
        const int row = bb * 4 + r;      /* = s*NKVH + h */
        const int s = row >> 3;
        float f = (float)positions[s] * invf[i];
        float c = cosf(f), sn = sinf(f);
        const float* base = g_k + (size_t)row * HD;
        float x1 = base[i], x2 = base[i + 64];
        rows[r][i]      = x1 * c - x2 * sn;
        rows[r][i + 64] = x2 * c + x1 * sn;
        __syncthreads();
        const int w = t & 63;            /* word within row */
        uint32_t hi, lo;
        split2(rows[r][2 * w], rows[r][2 * w + 1], hi, lo);
        ((uint32_t*)g_kh)[(size_t)row * 64 + w] = hi;
        ((uint32_t*)g_kl)[(size_t)row * 64 + w] = lo;
    } else {
        /* V j-pair pack */
        int i = (b - RQ_BLOCKS - RK_BLOCKS) * 256 + t;
        int p = i / KVDIM, x = i % KVDIM;
        float v0 = g_v[(size_t)(2 * p) * KVDIM + x];
        float v1 = g_v[(size_t)(2 * p + 1) * KVDIM + x];
        uint32_t hi, lo;
        split2(v0, v1, hi, lo);
        g_vph[i] = hi;
        g_vpl[i] = lo;
    }
}

/* ------- TF32 GEMM: 128x256 CTA, 16 warps (64x32 each), 4-stage cp.async (R15) ------- */

#define GBM 128
#define GBN 256
#define GBK 32
#define ASTR 36
#define BSTR 264
#define A_STAGE (GBM*ASTR)
#define B_STAGE (GBK*BSTR)
#define STG 4
#define GEMM_SMEM (STG*(A_STAGE+B_STAGE)*4)   /* 208896 B */

__device__ __forceinline__ void cp_async16(const void* smem_gen, const void* gptr) {
    uint32_t s = (uint32_t)__cvta_generic_to_shared(smem_gen);
    asm volatile("cp.async.cg.shared.global [%0], [%1], 16;" :: "r"(s), "l"(gptr));
}

__device__ __forceinline__ void gemm_body(
    const float* __restrict__ A, const float* __restrict__ B, float* __restrict__ C,
    int ldb, int ldc, int K, int bm0, int bn0, float* sm)
{
    float* As = sm;
    float* Bs = sm + STG * A_STAGE;

    const int tid  = threadIdx.x;
    const int lane = tid & 31;
    const int wid  = tid >> 5;
    const int wm   = (wid & 1) * 64;
    const int wn   = (wid >> 1) * 32;
    const int t4   = lane & 3;
    const int g    = lane >> 2;

    float acc[4][4][4];
    #pragma unroll
    for (int i = 0; i < 4; i++)
        #pragma unroll
        for (int j = 0; j < 4; j++)
            #pragma unroll
            for (int r = 0; r < 4; r++) acc[i][j][r] = 0.f;

    const int ar = tid >> 2;
    const int ac = (tid & 3) * 2;
    const int br = tid >> 4;
    const int bc = tid & 15;

    const int T = K / GBK;

    #define STAGE_TILE(ti, buf) do {                                              \
        const int _k0 = (ti) * GBK;                                               \
        const float* _Ag = A + (size_t)(bm0 + ar) * K + _k0;                      \
        _Pragma("unroll")                                                         \
        for (int s = 0; s < 2; s++)                                               \
            cp_async16(&As[(buf)*A_STAGE + ar*ASTR + (ac + s)*4], _Ag + (ac + s)*4);\
        const float* _Bg = B + (size_t)(_k0 + br) * ldb + bn0;                    \
        _Pragma("unroll")                                                         \
        for (int s = 0; s < 4; s++)                                               \
            cp_async16(&Bs[(buf)*B_STAGE + br*BSTR + (bc + s*16)*4], _Bg + (bc + s*16)*4);\
    } while (0)

    STAGE_TILE(0, 0);
    asm volatile("cp.async.commit_group;");
    STAGE_TILE(1, 1);
    asm volatile("cp.async.commit_group;");

    for (int t = 0; t < T; t++) {
        const int buf = t & 3;
        if (t + 2 < T)
            STAGE_TILE(t + 2, (t + 2) & 3);
        asm volatile("cp.async.commit_group;");
        asm volatile("cp.async.wait_group 2;");
        __syncthreads();

        const uint32_t* Ab = (const uint32_t*)(As + buf * A_STAGE);
        const uint32_t* Bb = (const uint32_t*)(Bs + buf * B_STAGE);

        #pragma unroll
        for (int ks = 0; ks < 4; ks++) {
            const int kk = ks * 8;
            uint32_t a[4][4], b[4][2];
            #pragma unroll
            for (int i = 0; i < 4; i++) {
                const int mr = wm + i * 16 + g;
                a[i][0] = Ab[mr * ASTR + kk + t4];
                a[i][1] = Ab[(mr + 8) * ASTR + kk + t4];
                a[i][2] = Ab[mr * ASTR + kk + t4 + 4];
                a[i][3] = Ab[(mr + 8) * ASTR + kk + t4 + 4];
            }
            #pragma unroll
            for (int j = 0; j < 4; j++) {
                const int nc = wn + j * 8 + g;
                b[j][0] = Bb[(kk + t4) * BSTR + nc];
                b[j][1] = Bb[(kk + t4 + 4) * BSTR + nc];
            }
            #pragma unroll
            for (int i = 0; i < 4; i++)
                #pragma unroll
                for (int j = 0; j < 4; j++) {
                    asm volatile(
                        "mma.sync.aligned.m16n8k8.row.col.f32.tf32.tf32.f32 "
                        "{%0,%1,%2,%3}, {%4,%5,%6,%7}, {%8,%9}, {%0,%1,%2,%3};"
                        : "+f"(acc[i][j][0]), "+f"(acc[i][j][1]),
                          "+f"(acc[i][j][2]), "+f"(acc[i][j][3])
                        : "r"(a[i][0]), "r"(a[i][1]), "r"(a[i][2]), "r"(a[i][3]),
                          "r"(b[j][0]), "r"(b[j][1]));
                }
        }
    }
    #undef STAGE_TILE

    #pragma unroll
    for (int i = 0; i < 4; i++) {
        int row0 = bm0 + wm + i * 16 + g;
        #pragma unroll
        for (int j = 0; j < 4; j++) {
            int col = bn0 + wn + j * 8 + 2 * t4;
            *(float2*)(C + (size_t)row0 * ldc + col)       = make_float2(acc[i][j][0], acc[i][j][1]);
            *(float2*)(C + (size_t)(row0 + 8) * ldc + col) = make_float2(acc[i][j][2], acc[i][j][3]);
        }
    }
}

__global__ __launch_bounds__(512, 1) void qkv_gemm_kernel()
{
    extern __shared__ float sm[];
    const int bx = blockIdx.x;
    const int bm0 = blockIdx.y * GBM;
    if (bx < 16)
        gemm_body(g_hs, g_wq, g_q, QDIM, QDIM, HIDDEN, bm0, bx * GBN, sm);
    else if (bx < 20)
        gemm_body(g_hs, g_wk, g_k, KVDIM, KVDIM, HIDDEN, bm0, (bx - 16) * GBN, sm);
    else
        gemm_body(g_hs, g_wv, g_v, KVDIM, KVDIM, HIDDEN, bm0, (bx - 20) * GBN, sm);
}

__global__ __launch_bounds__(512, 1) void o_gemm_kernel(float* __restrict__ out)
{
    extern __shared__ float sm[];
    gemm_body(g_attn, g_wo, out, HIDDEN, HIDDEN, QDIM, blockIdx.y * GBM, blockIdx.x * GBN, sm);
}

/* --------- Attention: bf16x3 mma flash, pre-split K/V + 2-stage cp.async pipeline ------ */
#define AQT 128
#define AKT 64
#define KPAD 68
#define VPAD 136
#define QW   (AQT*KPAD)
#define KVW  4352
#define STGW (4*KVW)
#define ATT_SMEM ((2*QW + 2*STGW)*4)   /* 208896 B */

#define MMA_BF16(c, a0,a1,a2,a3, b0,b1)                                      \
    asm volatile("mma.sync.aligned.m16n8k16.row.col.f32.bf16.bf16.f32 "      \
        "{%0,%1,%2,%3}, {%4,%5,%6,%7}, {%8,%9}, {%0,%1,%2,%3};"              \
        : "+f"(c[0]), "+f"(c[1]), "+f"(c[2]), "+f"(c[3])                     \
        : "r"(a0), "r"(a1), "r"(a2), "r"(a3), "r"(b0), "r"(b1))

__global__ __launch_bounds__(256, 1) void attn_mma_kernel(const float* __restrict__ sink)
{
    extern __shared__ uint32_t smw[];
    uint32_t* Qh = smw;
    uint32_t* Ql = Qh + QW;

    const int h   = blockIdx.y;
    const int q0  = blockIdx.x * AQT;
    const int kvh = h >> 2;
    const int tid = threadIdx.x;
    const int lane = tid & 31;
    const int wid  = tid >> 5;
    const int wrow = wid * 16;
    const int t4   = lane & 3;
    const int g    = lane >> 2;

    {
        const float* Qg = g_q + (size_t)q0 * QDIM + h * HD;
        #pragma unroll
        for (int it = 0; it < 16; it++) {
            int slot = tid + it * 256;
            int r = slot >> 5, d4 = slot & 31;
            float4 v = *(const float4*)(Qg + (size_t)r * QDIM + d4 * 4);
            uint32_t h01, l01, h23, l23;
            split2(v.x, v.y, h01, l01);
            split2(v.z, v.w, h23, l23);
            Qh[r * KPAD + d4 * 2]     = h01;
            Qh[r * KPAD + d4 * 2 + 1] = h23;
            Ql[r * KPAD + d4 * 2]     = l01;
            Ql[r * KPAD + d4 * 2 + 1] = l23;
        }
    }

    float o[16][4];
    #pragma unroll
    for (int i = 0; i < 16; i++)
        #pragma unroll
        for (int r = 0; r < 4; r++) o[i][r] = 0.f;
    float l0 = 0.f, l1 = 0.f;

    int jlo = q0 - (WINDOW - 1);
    if (jlo < 0) jlo = 0;
    const int kt0 = (jlo / AKT) * AKT;
    const int ktend = q0 + AQT;

    const int qi0 = q0 + wrow + g;
    const int qi1 = qi0 + 8;

    #define ATT_STAGE(kt, sb) do {                                                      \
        uint32_t* _s = smw + 2 * QW + (sb) * STGW;                                      \
        _Pragma("unroll")                                                               \
        for (int s = 0; s < 8; s++) {            /* K: 2048 chunks */                   \
            int c = tid + s * 256;                                                      \
            int arr = c >> 10, idx = c & 1023;                                          \
            int row = idx >> 4, ch = idx & 15;                                          \
            const __nv_bfloat16* src = (arr ? g_kl : g_kh)                              \
                + (size_t)((kt) + row) * KVDIM + kvh * HD + ch * 8;                     \
            cp_async16(_s + arr * KVW + row * KPAD + ch * 4, src);                      \
        }                                                                               \
        _Pragma("unroll")                                                               \
        for (int s = 0; s < 8; s++) {            /* V: 2048 chunks */                   \
            int c = tid + s * 256;                                                      \
            int arr = c >> 10, idx = c & 1023;                                          \
            int rp = idx >> 5, ch = idx & 31;                                           \
            const uint32_t* src = (arr ? g_vpl : g_vph)                                 \
                + (size_t)((kt) / 2 + rp) * KVDIM + kvh * HD + ch * 4;                  \
            cp_async16(_s + 2 * KVW + arr * KVW + rp * VPAD + ch * 4, src);             \
        }                                                                               \
    } while (0)

    ATT_STAGE(kt0, 0);
    asm volatile("cp.async.commit_group;");

    int it = 0;
    for (int kt = kt0; kt < ktend; kt += AKT, it++) {
        __syncthreads();
        if (kt + AKT < ktend)
            ATT_STAGE(kt + AKT, (it + 1) & 1);
        asm volatile("cp.async.commit_group;");
        asm volatile("cp.async.wait_group 1;");
        __syncthreads();

        const uint32_t* Kh = smw + 2 * QW + (it & 1) * STGW;
        const uint32_t* Kl = Kh + KVW;
        const uint32_t* Vh = Kh + 2 * KVW;
        const uint32_t* Vl = Kh + 3 * KVW;

        float s[8][4];
        #pragma unroll
        for (int nt = 0; nt < 8; nt++)
            #pragma unroll
            for (int r = 0; r < 4; r++) s[nt][r] = 0.f;

        #pragma unroll
        for (int kk = 0; kk < 8; kk++) {
            const int kw = kk * 8;
            uint32_t ah0 = Qh[(wrow + g)     * KPAD + kw + t4];
            uint32_t ah1 = Qh[(wrow + g + 8) * KPAD + kw + t4];
            uint32_t ah2 = Qh[(wrow + g)     * KPAD + kw + t4 + 4];
            uint32_t ah3 = Qh[(wrow + g + 8) * KPAD + kw + t4 + 4];
            uint32_t al0 = Ql[(wrow + g)     * KPAD + kw + t4];
            uint32_t al1 = Ql[(wrow + g + 8) * KPAD + kw + t4];
            uint32_t al2 = Ql[(wrow + g)     * KPAD + kw + t4 + 4];
            uint32_t al3 = Ql[(wrow + g + 8) * KPAD + kw + t4 + 4];
            #pragma unroll
            for (int nt = 0; nt < 8; nt++) {
                const int krow = nt * 8 + g;
                uint32_t bh0 = Kh[krow * KPAD + kw + t4];
                uint32_t bh1 = Kh[krow * KPAD + kw + t4 + 4];
                uint32_t bl0 = Kl[krow * KPAD + kw + t4];
                uint32_t bl1 = Kl[krow * KPAD + kw + t4 + 4];
                MMA_BF16(s[nt], ah0, ah1, ah2, ah3, bh0, bh1);
                MMA_BF16(s[nt], ah0, ah1, ah2, ah3, bl0, bl1);
                MMA_BF16(s[nt], al0, al1, al2, al3, bh0, bh1);
            }
        }

        #pragma unroll
        for (int nt = 0; nt < 8; nt++) {
            int c0 = kt + nt * 8 + 2 * t4;
            int c1 = c0 + 1;
            float p0 = (c0 <= qi0 && qi0 - c0 < WINDOW) ? __expf(s[nt][0] * SCALING) : 0.f;
            float p1 = (c1 <= qi0 && qi0 - c1 < WINDOW) ? __expf(s[nt][1] * SCALING) : 0.f;
            float p2 = (c0 <= qi1 && qi1 - c0 < WINDOW) ? __expf(s[nt][2] * SCALING) : 0.f;
            float p3 = (c1 <= qi1 && qi1 - c1 < WINDOW) ? __expf(s[nt][3] * SCALING) : 0.f;
            l0 += p0 + p1;
            l1 += p2 + p3;
            s[nt][0] = p0; s[nt][1] = p1; s[nt][2] = p2; s[nt][3] = p3;
        }

        #pragma unroll
        for (int ks = 0; ks < 4; ks++) {
            uint32_t ah0, al0, ah1, al1, ah2, al2, ah3, al3;
            split2(s[2*ks][0],   s[2*ks][1],   ah0, al0);
            split2(s[2*ks][2],   s[2*ks][3],   ah1, al1);
            split2(s[2*ks+1][0], s[2*ks+1][1], ah2, al2);
            split2(s[2*ks+1][2], s[2*ks+1][3], ah3, al3);
            #pragma unroll
            for (int nt = 0; nt < 16; nt++) {
                uint32_t bh0 = Vh[(ks * 8 + t4)     * VPAD + nt * 8 + g];
                uint32_t bh1 = Vh[(ks * 8 + t4 + 4) * VPAD + nt * 8 + g];
                uint32_t bl0 = Vl[(ks * 8 + t4)     * VPAD + nt * 8 + g];
                uint32_t bl1 = Vl[(ks * 8 + t4 + 4) * VPAD + nt * 8 + g];
                MMA_BF16(o[nt], ah0, ah1, ah2, ah3, bh0, bh1);
                MMA_BF16(o[nt], ah0, ah1, ah2, ah3, bl0, bl1);
                MMA_BF16(o[nt], al0, al1, al2, al3, bh0, bh1);
            }
        }
    }
    #undef ATT_STAGE

    l0 += __shfl_xor_sync(0xffffffffu, l0, 1);
    l0 += __shfl_xor_sync(0xffffffffu, l0, 2);
    l1 += __shfl_xor_sync(0xffffffffu, l1, 1);
    l1 += __shfl_xor_sync(0xffffffffu, l1, 2);
    float sk = __expf(sink[h]);
    float inv0 = 1.0f / (l0 + sk);
    float inv1 = 1.0f / (l1 + sk);

    float* out0 = g_attn + (size_t)qi0 * QDIM + h * HD;
    float* out1 = g_attn + (size_t)qi1 * QDIM + h * HD;
    #pragma unroll
    for (int nt = 0; nt < 16; nt++) {
        int d = nt * 8 + 2 * t4;
        *(float2*)(out0 + d) = make_float2(roundtf(o[nt][0] * inv0), roundtf(o[nt][1] * inv0));
        *(float2*)(out1 + d) = make_float2(roundtf(o[nt][2] * inv1), roundtf(o[nt][3] * inv1));
    }
}

/* ------------------------- launch ------------------------- */
extern "C" void kernel_launch(void* const* d_in, const int* in_sizes, int n_in,
                              void* d_out, int out_size)
{
    const float* hs   = (const float*)d_in[0];
    const int*   pos  = (const int*)d_in[1];
    const float* wq   = (const float*)d_in[2];
    const float* wk   = (const float*)d_in[3];
    const float* wv   = (const float*)d_in[4];
    const float* wo   = (const float*)d_in[5];
    const float* sink = (const float*)d_in[6];
    float* out = (float*)d_out;

    cudaFuncSetAttribute(qkv_gemm_kernel, cudaFuncAttributeMaxDynamicSharedMemorySize, GEMM_SMEM);
    cudaFuncSetAttribute(o_gemm_kernel,  cudaFuncAttributeMaxDynamicSharedMemorySize, GEMM_SMEM);
    cudaFuncSetAttribute(attn_mma_kernel, cudaFuncAttributeMaxDynamicSharedMemorySize, ATT_SMEM);

    /* tf32 pre-rounding of all GEMM inputs (one launch) */
    round_all_kernel<<<RB_HS+RB_WQ+RB_WK+RB_WV+RB_WO, 256>>>(hs, wq, wk, wv, wo);

    /* fused QKV projection */
    qkv_gemm_kernel<<<dim3(24, SEQ / GBM), 512, GEMM_SMEM>>>();

    /* merged prep: rope_q | rope_k + K split | V pack (one launch) */
    prep_kernel<<<RQ_BLOCKS + RK_BLOCKS + PV_BLOCKS, 256>>>(pos);

    /* attention (bf16x3 tensor cores, pipelined pre-split K/V) */
    attn_mma_kernel<<<dim3(SEQ / AQT, NQH), 256, ATT_SMEM>>>(sink);

    /* output projection */
    o_gemm_kernel<<<dim3(HIDDEN / GBN, SEQ / GBM), 512, GEMM_SMEM>>>(out);
}